// round 6
// baseline (speedup 1.0000x reference)
#include <cuda_runtime.h>

// GraphNorm: x (131072, 256) fp32, 64 graphs x 2048 rows x 256 units.
// out = gamma * (x - mean_g,u) / (std_g,u + 1e-5) + beta.
//
// Fused, small-block design: 128-thread blocks, 16 units/block,
// grid (16, 64) = 1024 blocks -> ALL co-resident (8 blocks/SM fit at 64 regs),
// single balanced wave (~7 blocks/SM, ~1% imbalance), so per-block barrier
// phases are hidden by neighboring blocks' streaming.
//  - pass1: 32 rows/thread, v8 evict_last loads in batches of 4
//  - pass2: 16 pipelined row-pairs, 6 v8 evict_first loads in flight,
//    mean/inv from smem float2, st.global.cs.v4 stores.

#define UNITS   256
#define BATCH   64
#define NPG     2048
#define UB      16              // units per block
#define NWARPS  4
#define THREADS 128
#define VEC     8
#define EPS     1e-5f
// 64 rows are covered per block-iteration (4 warps x 16 row-subgroups)
#define RSTRIDE ((size_t)64 * UNITS)
#define P1_ITERS 32             // 2048 / 64
#define P2_PAIRS 16

__device__ __forceinline__ void ld_v8_evict_last(const float* p, float* r) {
    asm volatile("ld.global.L2::evict_last.v8.b32 {%0,%1,%2,%3,%4,%5,%6,%7}, [%8];"
                 : "=f"(r[0]), "=f"(r[1]), "=f"(r[2]), "=f"(r[3]),
                   "=f"(r[4]), "=f"(r[5]), "=f"(r[6]), "=f"(r[7])
                 : "l"(p));
}
__device__ __forceinline__ void ld_v8_evict_first(const float* p, float* r) {
    asm volatile("ld.global.L2::evict_first.v8.b32 {%0,%1,%2,%3,%4,%5,%6,%7}, [%8];"
                 : "=f"(r[0]), "=f"(r[1]), "=f"(r[2]), "=f"(r[3]),
                   "=f"(r[4]), "=f"(r[5]), "=f"(r[6]), "=f"(r[7])
                 : "l"(p));
}
__device__ __forceinline__ void st_v4_cs(float* p, float a, float b, float c, float d) {
    asm volatile("st.global.cs.v4.f32 [%0], {%1,%2,%3,%4};"
                 :: "l"(p), "f"(a), "f"(b), "f"(c), "f"(d));
}

__global__ void __launch_bounds__(THREADS, 8)
graphnorm_kernel(const float* __restrict__ x,
                 const float* __restrict__ gamma,
                 const float* __restrict__ beta,
                 float* __restrict__ out)
{
    const int uc   = blockIdx.x;           // unit chunk 0..15 (16 units each)
    const int g    = blockIdx.y;           // graph 0..63
    const int lane = threadIdx.x & 31;
    const int w    = threadIdx.x >> 5;     // warp 0..3
    const int ug   = lane & 1;             // unit subgroup 0..1 (8 units each)
    const int rg   = lane >> 1;            // row subgroup 0..15

    // per-thread base: graph g, row (w*16+rg), units uc*16 + ug*8
    const size_t base = (size_t)g * NPG * UNITS
                      + (size_t)(w * 16 + rg) * UNITS
                      + (size_t)uc * UB + (size_t)ug * VEC;
    const float* xb = x + base;

    // ---------------- pass 1: sum / sumsq (32 rows, batches of 4) ----------------
    float sum[VEC], sq[VEC];
    #pragma unroll
    for (int j = 0; j < VEC; ++j) { sum[j] = 0.f; sq[j] = 0.f; }

    #pragma unroll
    for (int b = 0; b < P1_ITERS / 4; ++b) {
        float v[4][VEC];
        #pragma unroll
        for (int k = 0; k < 4; ++k)
            ld_v8_evict_last(xb + (size_t)(b * 4 + k) * RSTRIDE, v[k]);
        #pragma unroll
        for (int k = 0; k < 4; ++k)
            #pragma unroll
            for (int j = 0; j < VEC; ++j) {
                sum[j] += v[k][j];
                sq[j] = fmaf(v[k][j], v[k][j], sq[j]);
            }
    }

    // warp reduce over the 16 row-subgroups (lane bits 1..4)
    #pragma unroll
    for (int m = 2; m <= 16; m <<= 1) {
        #pragma unroll
        for (int j = 0; j < VEC; ++j) {
            sum[j] += __shfl_xor_sync(0xffffffffu, sum[j], m);
            sq[j]  += __shfl_xor_sync(0xffffffffu, sq[j],  m);
        }
    }

    __shared__ float s_sum[NWARPS][UB];
    __shared__ float s_sq [NWARPS][UB];
    if (lane < 2) {                        // lanes 0,1 hold the two unit groups
        #pragma unroll
        for (int j = 0; j < VEC; ++j) {
            s_sum[w][ug * VEC + j] = sum[j];
            s_sq [w][ug * VEC + j] = sq[j];
        }
    }
    __syncthreads();

    __shared__ float2 s_mi[UB];            // {mean, inv} per unit in chunk
    if (w == 0 && lane < UB) {
        float a = 0.f, b = 0.f;
        #pragma unroll
        for (int k = 0; k < NWARPS; ++k) {
            a += s_sum[k][lane];
            b += s_sq [k][lane];
        }
        const float invn = 1.0f / (float)NPG;
        const float mean = a * invn;
        float var = fmaf(-mean, mean, b * invn);
        var = fmaxf(var, 0.0f);
        s_mi[lane] = make_float2(mean, 1.0f / (sqrtf(var) + EPS));
    }
    __syncthreads();

    // ---------------- pass 2: normalize + affine (pipelined pairs) ----------------
    const float* gb = gamma + base;
    const float* bb = beta  + base;
    float*       ob = out   + base;

    #pragma unroll
    for (int p = 0; p < P2_PAIRS; ++p) {
        const size_t off0 = (size_t)(2 * p)     * RSTRIDE;
        const size_t off1 = (size_t)(2 * p + 1) * RSTRIDE;
        float v0[VEC], ga0[VEC], be0[VEC];
        float v1[VEC], ga1[VEC], be1[VEC];
        ld_v8_evict_first(xb + off0, v0);      // 2nd read of x: L2 hit, then drop
        ld_v8_evict_first(xb + off1, v1);
        ld_v8_evict_first(gb + off0, ga0);
        ld_v8_evict_first(gb + off1, ga1);
        ld_v8_evict_first(bb + off0, be0);
        ld_v8_evict_first(bb + off1, be1);

        #pragma unroll
        for (int j = 0; j < VEC; ++j) {
            const float2 mi = s_mi[ug * VEC + j];
            v0[j] = fmaf((v0[j] - mi.x) * mi.y, ga0[j], be0[j]);
            v1[j] = fmaf((v1[j] - mi.x) * mi.y, ga1[j], be1[j]);
        }
        st_v4_cs(ob + off0,     v0[0], v0[1], v0[2], v0[3]);
        st_v4_cs(ob + off0 + 4, v0[4], v0[5], v0[6], v0[7]);
        st_v4_cs(ob + off1,     v1[0], v1[1], v1[2], v1[3]);
        st_v4_cs(ob + off1 + 4, v1[4], v1[5], v1[6], v1[7]);
    }
}

extern "C" void kernel_launch(void* const* d_in, const int* in_sizes, int n_in,
                              void* d_out, int out_size) {
    const float* x     = (const float*)d_in[0];
    const float* gamma = (const float*)d_in[1];
    const float* beta  = (const float*)d_in[2];
    float* out = (float*)d_out;

    dim3 grid(UNITS / UB, BATCH);   // (16, 64) = 1024 blocks, all co-resident
    graphnorm_kernel<<<grid, THREADS>>>(x, gamma, beta, out);
}

// round 7
// speedup vs baseline: 1.2069x; 1.2069x over previous
#include <cuda_runtime.h>

// GraphNorm: x (131072, 256) fp32, 64 graphs x 2048 rows x 256 units.
// out = gamma * (x - mean_g,u) / (std_g,u + 1e-5) + beta.
//
// Fused kernel, 512-thread blocks, 2 blocks/SM co-resident:
//  - concurrent x footprint 296 x 256KB = 76MB < L2 -> pass2 x re-read hits L2
//  - when one block is in its reduction phase, the SM-mate keeps issuing loads
//  - tile is 32 units wide (128B rows) -> fully coalesced v8 warp loads
//  - only 2 __syncthreads total (shuffle -> smem -> one-warp finalize)
//  - pass1: batch-4 v8 evict_last; pass2: pipelined pairs, 6 v8 evict_first
//    in flight; st.global.cs.v4 stores.

#define UNITS   256
#define BATCH   64
#define NPG     2048
#define UB      32              // units per block
#define NWARPS  16
#define THREADS 512
#define VEC     8
#define EPS     1e-5f
// 128 rows covered per block iteration (16 warps x 8 row-subgroups)
#define RSTRIDE ((size_t)128 * UNITS)
#define P1_ITERS 16             // 2048 / 128
#define P2_PAIRS 8

__device__ __forceinline__ void ld_v8_evict_last(const float* p, float* r) {
    asm volatile("ld.global.L2::evict_last.v8.b32 {%0,%1,%2,%3,%4,%5,%6,%7}, [%8];"
                 : "=f"(r[0]), "=f"(r[1]), "=f"(r[2]), "=f"(r[3]),
                   "=f"(r[4]), "=f"(r[5]), "=f"(r[6]), "=f"(r[7])
                 : "l"(p));
}
__device__ __forceinline__ void ld_v8_evict_first(const float* p, float* r) {
    asm volatile("ld.global.L2::evict_first.v8.b32 {%0,%1,%2,%3,%4,%5,%6,%7}, [%8];"
                 : "=f"(r[0]), "=f"(r[1]), "=f"(r[2]), "=f"(r[3]),
                   "=f"(r[4]), "=f"(r[5]), "=f"(r[6]), "=f"(r[7])
                 : "l"(p));
}
__device__ __forceinline__ void st_v4_cs(float* p, float a, float b, float c, float d) {
    asm volatile("st.global.cs.v4.f32 [%0], {%1,%2,%3,%4};"
                 :: "l"(p), "f"(a), "f"(b), "f"(c), "f"(d));
}

__global__ void __launch_bounds__(THREADS, 2)
graphnorm_kernel(const float* __restrict__ x,
                 const float* __restrict__ gamma,
                 const float* __restrict__ beta,
                 float* __restrict__ out)
{
    const int uc   = blockIdx.x;           // unit chunk 0..7 (32 units)
    const int g    = blockIdx.y;           // graph 0..63
    const int lane = threadIdx.x & 31;
    const int w    = threadIdx.x >> 5;     // warp 0..15
    const int ug   = lane & 3;             // 8-unit subgroup 0..3
    const int rg   = lane >> 2;            // row subgroup 0..7

    // per-thread base: graph g, row (w*8+rg), units uc*32 + ug*8
    const size_t base = (size_t)g * NPG * UNITS
                      + (size_t)(w * 8 + rg) * UNITS
                      + (size_t)uc * UB + (size_t)ug * VEC;
    const float* xb = x + base;

    // ---------------- pass 1: sum / sumsq (16 rows, batches of 4) ----------------
    float sum[VEC], sq[VEC];
    #pragma unroll
    for (int j = 0; j < VEC; ++j) { sum[j] = 0.f; sq[j] = 0.f; }

    #pragma unroll
    for (int b = 0; b < P1_ITERS / 4; ++b) {
        float v[4][VEC];
        #pragma unroll
        for (int k = 0; k < 4; ++k)
            ld_v8_evict_last(xb + (size_t)(b * 4 + k) * RSTRIDE, v[k]);
        #pragma unroll
        for (int k = 0; k < 4; ++k)
            #pragma unroll
            for (int j = 0; j < VEC; ++j) {
                sum[j] += v[k][j];
                sq[j] = fmaf(v[k][j], v[k][j], sq[j]);
            }
    }

    // warp reduce over 8 row-subgroups (lane bits 2..4); lanes 0..3 hold results
    #pragma unroll
    for (int m = 4; m <= 16; m <<= 1) {
        #pragma unroll
        for (int j = 0; j < VEC; ++j) {
            sum[j] += __shfl_xor_sync(0xffffffffu, sum[j], m);
            sq[j]  += __shfl_xor_sync(0xffffffffu, sq[j],  m);
        }
    }

    __shared__ float s_sum[NWARPS][UB];
    __shared__ float s_sq [NWARPS][UB];
    if (lane < 4) {
        #pragma unroll
        for (int j = 0; j < VEC; ++j) {
            s_sum[w][ug * VEC + j] = sum[j];
            s_sq [w][ug * VEC + j] = sq[j];
        }
    }
    __syncthreads();

    // single-warp finalize: lane u sums 16 warp partials (conflict-free LDS)
    __shared__ float2 s_mi[UB];            // {mean, inv} per unit in chunk
    if (w == 0) {
        float a = 0.f, b = 0.f;
        #pragma unroll
        for (int k = 0; k < NWARPS; ++k) {
            a += s_sum[k][lane];
            b += s_sq [k][lane];
        }
        const float invn = 1.0f / (float)NPG;
        const float mean = a * invn;
        float var = fmaf(-mean, mean, b * invn);
        var = fmaxf(var, 0.0f);
        s_mi[lane] = make_float2(mean, 1.0f / (sqrtf(var) + EPS));
    }
    __syncthreads();

    // ---------------- pass 2: normalize + affine (pipelined pairs) ----------------
    const float* gb = gamma + base;
    const float* bb = beta  + base;
    float*       ob = out   + base;

    #pragma unroll
    for (int p = 0; p < P2_PAIRS; ++p) {
        const size_t off0 = (size_t)(2 * p)     * RSTRIDE;
        const size_t off1 = (size_t)(2 * p + 1) * RSTRIDE;
        float v0[VEC], ga0[VEC], be0[VEC];
        float v1[VEC], ga1[VEC], be1[VEC];
        ld_v8_evict_first(xb + off0, v0);      // 2nd read of x: L2 hit, then drop
        ld_v8_evict_first(xb + off1, v1);
        ld_v8_evict_first(gb + off0, ga0);
        ld_v8_evict_first(gb + off1, ga1);
        ld_v8_evict_first(bb + off0, be0);
        ld_v8_evict_first(bb + off1, be1);

        #pragma unroll
        for (int j = 0; j < VEC; ++j) {
            const float2 mi = s_mi[ug * VEC + j];
            v0[j] = fmaf((v0[j] - mi.x) * mi.y, ga0[j], be0[j]);
            v1[j] = fmaf((v1[j] - mi.x) * mi.y, ga1[j], be1[j]);
        }
        st_v4_cs(ob + off0,     v0[0], v0[1], v0[2], v0[3]);
        st_v4_cs(ob + off0 + 4, v0[4], v0[5], v0[6], v0[7]);
        st_v4_cs(ob + off1,     v1[0], v1[1], v1[2], v1[3]);
        st_v4_cs(ob + off1 + 4, v1[4], v1[5], v1[6], v1[7]);
    }
}

extern "C" void kernel_launch(void* const* d_in, const int* in_sizes, int n_in,
                              void* d_out, int out_size) {
    const float* x     = (const float*)d_in[0];
    const float* gamma = (const float*)d_in[1];
    const float* beta  = (const float*)d_in[2];
    float* out = (float*)d_out;

    dim3 grid(UNITS / UB, BATCH);   // (8, 64), 512 blocks, 2 per SM
    graphnorm_kernel<<<grid, THREADS>>>(x, gamma, beta, out);
}